// round 4
// baseline (speedup 1.0000x reference)
#include <cuda_runtime.h>

// RouterModel: N=32768 tokens, D=1024, P=2 paths.
// d = x . (W[:,0]-W[:,1]); path = d>=0 ? 0 : 1; gate = sigmoid(|d|)
// out = [x0 | x1 | xc], each [N, D] float32.

#define N_TOK 32768
#define DHID  1024
#define THREADS 256   // DHID/4 float4 lanes per row

__device__ float g_wdiff[DHID];

__global__ void wdiff_kernel(const float* __restrict__ W) {
    int i = blockIdx.x * blockDim.x + threadIdx.x;
    if (i < DHID) g_wdiff[i] = W[2 * i] - W[2 * i + 1];
}

__global__ __launch_bounds__(THREADS) void router_kernel(
    const float* __restrict__ x, float* __restrict__ out)
{
    const int n = blockIdx.x;
    const int t = threadIdx.x;

    // Load this thread's float4 slice of the token row (row stays in registers).
    const float4 v = reinterpret_cast<const float4*>(x + (size_t)n * DHID)[t];
    const float4 w = reinterpret_cast<const float4*>(g_wdiff)[t];

    // Partial dot with (W0 - W1)
    float p = v.x * w.x + v.y * w.y + v.z * w.z + v.w * w.w;

    // Warp reduce
    #pragma unroll
    for (int o = 16; o > 0; o >>= 1)
        p += __shfl_xor_sync(0xffffffffu, p, o);

    __shared__ float s[THREADS / 32];
    const int wid = t >> 5, lid = t & 31;
    if (lid == 0) s[wid] = p;
    __syncthreads();

    float d = 0.0f;
    #pragma unroll
    for (int i = 0; i < THREADS / 32; i++) d += s[i];   // smem broadcast, no conflict

    // gate = softmax max-prob = sigmoid(|d|); path 0 iff d >= 0 (argmax tie -> 0)
    const float g = 1.0f / (1.0f + expf(-fabsf(d)));
    const bool  path0 = (d >= 0.0f);

    const float4 sv   = make_float4(v.x * g, v.y * g, v.z * g, v.w * g);
    const float4 zero = make_float4(0.f, 0.f, 0.f, 0.f);

    const size_t row4   = (size_t)n * (DHID / 4) + t;            // float4 index
    const size_t sect4  = (size_t)N_TOK * (DHID / 4);
    float4* o = reinterpret_cast<float4*>(out);

    o[row4]             = path0 ? sv   : zero;   // x0
    o[sect4 + row4]     = path0 ? zero : sv;     // x1
    o[2 * sect4 + row4] = sv;                    // xc
}

extern "C" void kernel_launch(void* const* d_in, const int* in_sizes, int n_in,
                              void* d_out, int out_size) {
    const float* x = (const float*)d_in[0];   // [N, D] float32
    const float* W = (const float*)d_in[1];   // [D, 2] float32
    float* out = (float*)d_out;               // [3, N, D] float32

    wdiff_kernel<<<(DHID + 255) / 256, 256>>>(W);
    router_kernel<<<N_TOK, THREADS>>>(x, out);
}

// round 6
// speedup vs baseline: 1.0252x; 1.0252x over previous
#include <cuda_runtime.h>

// RouterModel: N=32768 tokens, D=1024, P=2 paths.
// d = x . (W[:,0]-W[:,1]); path = d>=0 ? 0 : 1; gate = sigmoid(|d|)
// out = [x0 | x1 | xc], each [N, D] float32. Single fused kernel:
// W is 8 KB -> L1/L2 resident; each thread loads its 2 interleaved float4s
// of W and folds the column subtraction into the partial dot.

#define N_TOK 32768
#define DHID  1024
#define THREADS 256   // DHID/4 float4 lanes per row

__global__ __launch_bounds__(THREADS) void router_kernel(
    const float* __restrict__ x, const float* __restrict__ W,
    float* __restrict__ out)
{
    const int n = blockIdx.x;
    const int t = threadIdx.x;

    // Streaming load of this thread's float4 slice of the token row (no reuse).
    const float4 v = __ldcs(reinterpret_cast<const float4*>(x + (size_t)n * DHID) + t);

    // W rows 4t..4t+3, layout [D,2] row-major: pairs (W0,W1) interleaved.
    // float4 index 2t -> (W[8t],W[8t+1],W[8t+2],W[8t+3]) etc. L1-hit after wave 1.
    const float4 wa = __ldg(reinterpret_cast<const float4*>(W) + 2 * t);
    const float4 wb = __ldg(reinterpret_cast<const float4*>(W) + 2 * t + 1);

    // Partial dot with (W0 - W1)
    float p = v.x * (wa.x - wa.y) + v.y * (wa.z - wa.w)
            + v.z * (wb.x - wb.y) + v.w * (wb.z - wb.w);

    // Warp reduce
    #pragma unroll
    for (int o = 16; o > 0; o >>= 1)
        p += __shfl_xor_sync(0xffffffffu, p, o);

    __shared__ float s[THREADS / 32];
    const int wid = t >> 5, lid = t & 31;
    if (lid == 0) s[wid] = p;
    __syncthreads();

    float d = 0.0f;
    #pragma unroll
    for (int i = 0; i < THREADS / 32; i++) d += s[i];   // broadcast, conflict-free

    // gate = softmax max-prob = sigmoid(|d|); path 0 iff d >= 0 (argmax tie -> 0)
    const float g = 1.0f / (1.0f + expf(-fabsf(d)));
    const bool  path0 = (d >= 0.0f);

    const float4 sv   = make_float4(v.x * g, v.y * g, v.z * g, v.w * g);
    const float4 zero = make_float4(0.f, 0.f, 0.f, 0.f);

    const size_t row4  = (size_t)n * (DHID / 4) + t;   // float4 index
    const size_t sect4 = (size_t)N_TOK * (DHID / 4);
    float4* o = reinterpret_cast<float4*>(out);

    // Streaming stores: evict-first in L2, outputs are write-once.
    __stcs(o + row4,             path0 ? sv   : zero);  // x0
    __stcs(o + sect4 + row4,     path0 ? zero : sv);    // x1
    __stcs(o + 2 * sect4 + row4, sv);                   // xc
}

extern "C" void kernel_launch(void* const* d_in, const int* in_sizes, int n_in,
                              void* d_out, int out_size) {
    const float* x = (const float*)d_in[0];   // [N, D] float32
    const float* W = (const float*)d_in[1];   // [D, 2] float32
    float* out = (float*)d_out;               // [3, N, D] float32

    router_kernel<<<N_TOK, THREADS>>>(x, W, out);
}